// round 16
// baseline (speedup 1.0000x reference)
#include <cuda_runtime.h>
#include <cuda_fp16.h>
#include <math.h>
#include <stdint.h>

#define PLANE 3145728            // 3072 * 1024
#define WELEMS 17825792          // 17 * 1024 * 1024

// ---------------- device scratch --------------------------------------------
__device__ float g_Y[PLANE];                 // pre-projection Y of current layer
__device__ float g_xt[17 * PLANE];           // xs[l] planes (fp32)
__device__ __half g_hX[2][PLANE];            // ping-pong fp16 X
__device__ __half g_hW[WELEMS];              // fp16 weights (W0 at 0, Ws at 1..16)

// ---------------- helpers -----------------------------------------------------
typedef unsigned long long u64p;

static __device__ __forceinline__ uint32_t smem_u32(const void* p) {
    return (uint32_t)__cvta_generic_to_shared(p);
}
static __device__ __forceinline__ void ldsm4(uint32_t* r, uint32_t addr) {
    asm volatile("ldmatrix.sync.aligned.m8n8.x4.shared.b16 {%0,%1,%2,%3}, [%4];"
        : "=r"(r[0]), "=r"(r[1]), "=r"(r[2]), "=r"(r[3]) : "r"(addr));
}
static __device__ __forceinline__ void mma16816(float* c, const uint32_t* a,
                                                uint32_t b0, uint32_t b1) {
    asm volatile("mma.sync.aligned.m16n8k16.row.col.f32.f16.f16.f32 "
        "{%0,%1,%2,%3}, {%4,%5,%6,%7}, {%8,%9}, {%0,%1,%2,%3};"
        : "+f"(c[0]), "+f"(c[1]), "+f"(c[2]), "+f"(c[3])
        : "r"(a[0]), "r"(a[1]), "r"(a[2]), "r"(a[3]), "r"(b0), "r"(b1));
}
static __device__ __forceinline__ u64p pk2(float x, float y) {
    u64p r; asm("mov.b64 %0, {%1,%2};" : "=l"(r) : "f"(x), "f"(y)); return r;
}
static __device__ __forceinline__ void upk2(u64p v, float& x, float& y) {
    asm("mov.b64 {%0,%1}, %2;" : "=f"(x), "=f"(y) : "l"(v));
}
static __device__ __forceinline__ u64p fma2(u64p a, u64p b, u64p c) {
    u64p d; asm("fma.rn.f32x2 %0, %1, %2, %3;" : "=l"(d) : "l"(a), "l"(b), "l"(c));
    return d;
}
static __device__ __forceinline__ u64p mul2(u64p a, u64p b) {
    u64p d; asm("mul.rn.f32x2 %0, %1, %2;" : "=l"(d) : "l"(a), "l"(b));
    return d;
}

// ---------------- weight conversion (fp16) -----------------------------------
__global__ void wconv_kernel(const float* __restrict__ W0, const float* __restrict__ Ws) {
    size_t i = (size_t)blockIdx.x * 256 + threadIdx.x;
    if (i >= (size_t)WELEMS) return;
    float v = (i < 1048576) ? W0[i] : Ws[i - 1048576];
    g_hW[i] = __float2half_rn(v);
}

// ---------------- prep: fp16 of input (ch2 transposed) -----------------------
__global__ void prep_kernel(const float* __restrict__ Xin) {
    int idx = blockIdx.x * 256 + threadIdx.x;
    if (idx >= PLANE) return;
    int d  = idx & 1023;
    int bc = idx >> 10;
    int c  = bc % 3;
    float v;
    if (c == 2) {
        int b = bc / 3;
        int dim = d >> 4, k = d & 15;
        v = Xin[((size_t)(b * 3 + 2)) * 1024 + k * 64 + dim];
    } else {
        v = Xin[idx];
    }
    g_hX[0][idx] = __float2half_rn(v);
}

// ---------------- fp16 mma.sync GEMM + fused epilogue ------------------------
// Tile 96x128 (256 CTAs), K-chunk 64, 3-stage cp.async, 8 warps (2M x 4N).
#define MAT_STRIDE_B 144                 // bytes per smem row (128B data + pad)
#define A_BYTES (96 * MAT_STRIDE_B)      // 13824
#define B_BYTES (128 * MAT_STRIDE_B)     // 18432
#define STAGE_BYTES (A_BYTES + B_BYTES)  // 32256
#define SMEM_TOTAL_G (3 * STAGE_BYTES)   // 96768

__global__ __launch_bounds__(256, 2) void tgemm_kernel(
    const float* __restrict__ bias, const float* __restrict__ hp, int layer)
{
    extern __shared__ __align__(16) char smem[];
    uint32_t sb = smem_u32(smem);

    int tid = threadIdx.x;
    int wid = tid >> 5, lane = tid & 31;
    int bx = blockIdx.x;
    int m0 = (bx >> 3) * 96;
    int n0 = (bx & 7) * 128;

    int par = layer & 1;
    const __half* srcA = g_hX[par] + (size_t)m0 * 1024;
    const __half* srcB = g_hW + (size_t)layer * 1048576 + (size_t)n0 * 1024;

    float acc[3][4][4];
#pragma unroll
    for (int i = 0; i < 3; i++)
#pragma unroll
        for (int j = 0; j < 4; j++)
#pragma unroll
            for (int k = 0; k < 4; k++) acc[i][j][k] = 0.f;

    auto issue = [&](int c, int st) {
#pragma unroll
        for (int u = 0; u < 7; u++) {
            int unit = tid + u * 256;        // 0..1791
            uint32_t dst;
            const __half* gp;
            if (unit < 768) {                // A: 96 rows x 8 segs
                int row = unit >> 3, seg = unit & 7;
                dst = sb + st * STAGE_BYTES + row * MAT_STRIDE_B + seg * 16;
                gp = srcA + (size_t)row * 1024 + c * 64 + seg * 8;
            } else {                         // B: 128 rows x 8 segs
                int t = unit - 768;
                int row = t >> 3, seg = t & 7;
                dst = sb + st * STAGE_BYTES + A_BYTES + row * MAT_STRIDE_B + seg * 16;
                gp = srcB + (size_t)row * 1024 + c * 64 + seg * 8;
            }
            asm volatile("cp.async.cg.shared.global [%0], [%1], 16;"
                :: "r"(dst), "l"(gp));
        }
        asm volatile("cp.async.commit_group;" ::: "memory");
    };

    issue(0, 0);
    issue(1, 1);

    int mw = (wid >> 2) * 48, nw = (wid & 3) * 32;
    int lrow = (lane & 7) + ((lane >> 3) & 1) * 8;
    int lcolB = ((lane >> 4) * 8) * 2;

    for (int c = 0; c < 16; c++) {
        int st = c % 3;
        if (c < 15) {
            asm volatile("cp.async.wait_group 1;" ::: "memory");
        } else {
            asm volatile("cp.async.wait_group 0;" ::: "memory");
        }
        __syncthreads();
        if (c + 2 < 16) issue(c + 2, (c + 2) % 3);

        uint32_t base = sb + st * STAGE_BYTES;
#pragma unroll
        for (int ks = 0; ks < 4; ks++) {
            int colb = ks * 32 + lcolB;
            uint32_t bh[2][4];
#pragma unroll
            for (int nb = 0; nb < 2; nb++)
                ldsm4(bh[nb], base + A_BYTES +
                              (nw + nb * 16 + lrow) * MAT_STRIDE_B + colb);
#pragma unroll
            for (int ma = 0; ma < 3; ma++) {
                uint32_t ah[4];
                ldsm4(ah, base + (mw + ma * 16 + lrow) * MAT_STRIDE_B + colb);
#pragma unroll
                for (int na = 0; na < 4; na++) {
                    int nb = na >> 1, hi = na & 1;
                    mma16816(acc[ma][na], ah, bh[nb][hi], bh[nb][2 + hi]);
                }
            }
        }
    }

    // ---- fused epilogue
    float hv = 0.f;
    const float* Xprev = nullptr;
    if (layer > 0) { hv = *hp; Xprev = g_xt + (size_t)(layer - 1) * PLANE; }
    float* PL = g_xt + (size_t)layer * PLANE;
    int opar = (layer + 1) & 1;
    int g = lane >> 2, t2 = (lane & 3) * 2;

#pragma unroll
    for (int ma = 0; ma < 3; ma++) {
#pragma unroll
        for (int na = 0; na < 4; na++) {
            int n = n0 + nw + na * 8 + t2;
            float2 b2 = make_float2(0.f, 0.f);
            if (layer > 0) b2 = *(const float2*)(bias + n);
#pragma unroll
            for (int hh = 0; hh < 2; hh++) {
                int m = m0 + mw + ma * 16 + g + hh * 8;
                float cx = acc[ma][na][hh * 2], cy = acc[ma][na][hh * 2 + 1];
                float2 y;
                if (layer > 0) {
                    float2 xo = *(const float2*)(Xprev + (size_t)m * 1024 + n);
                    y.x = xo.x + hv * fmaxf(cx + b2.x, 0.f);
                    y.y = xo.y + hv * fmaxf(cy + b2.y, 0.f);
                } else {
                    y.x = cx; y.y = cy;
                }
                if (m % 3 == 1) {          // S channel: no projection
                    *(float2*)(PL + (size_t)m * 1024 + n) = y;
                    __half2 h2;
                    h2.x = __float2half_rn(y.x);
                    h2.y = __float2half_rn(y.y);
                    *(__half2*)(&g_hX[opar][(size_t)m * 1024 + n]) = h2;
                } else {                   // U/V channels: polar input only
                    *(float2*)(g_Y + (size_t)m * 1024 + n) = y;
                }
            }
        }
    }
}

// ---------------- polar projection (NS, smem-op minimized) -------------------
#define PNW 4
__global__ __launch_bounds__(128) void polar_kernel(int plane, int nspecial,
                                                    int nclassic, float ca_s,
                                                    float cb_s, int opar) {
    __shared__ float AsP[PNW][16][68];
    __shared__ float MsP[PNW][3][16][20];

    int w = threadIdx.x >> 5, lane = threadIdx.x & 31;
    int idx = blockIdx.x * PNW + w;
    int b = idx >> 1, ch = (idx & 1) * 2;

    const float* src = g_Y + (size_t)(b * 3 + ch) * 1024;
    size_t doff = (size_t)(b * 3 + ch) * 1024;
    float* dst = g_xt + (size_t)plane * PLANE + doff;

    float (*A)[68]  = AsP[w];
    float (*Ym)[20] = MsP[w][0];
    float (*Zm)[20] = MsP[w][1];
    float (*Tm)[20] = MsP[w][2];

    int r0 = lane * 2;
#pragma unroll
    for (int qq = 0; qq < 4; qq++) {
        float4 v0 = *(const float4*)(src + r0 * 16 + qq * 4);
        float4 v1 = *(const float4*)(src + (r0 + 1) * 16 + qq * 4);
        *(float2*)&A[qq * 4 + 0][r0] = make_float2(v0.x, v1.x);
        *(float2*)&A[qq * 4 + 1][r0] = make_float2(v0.y, v1.y);
        *(float2*)&A[qq * 4 + 2][r0] = make_float2(v0.z, v1.z);
        *(float2*)&A[qq * 4 + 3][r0] = make_float2(v0.w, v1.w);
    }
    __syncwarp();

    int i0 = (lane >> 2) * 2, j0 = (lane & 3) * 4;

    u64p gp0[4], gp1[4];
#pragma unroll
    for (int t = 0; t < 4; t++) { gp0[t] = 0ull; gp1[t] = 0ull; }
#pragma unroll
    for (int r = 0; r < 64; r += 4) {
        ulonglong2 a0 = *(const ulonglong2*)&A[i0][r];
        ulonglong2 a1 = *(const ulonglong2*)&A[i0 + 1][r];
#pragma unroll
        for (int t = 0; t < 4; t++) {
            ulonglong2 aj = *(const ulonglong2*)&A[j0 + t][r];
            gp0[t] = fma2(a0.x, aj.x, gp0[t]);
            gp0[t] = fma2(a0.y, aj.y, gp0[t]);
            gp1[t] = fma2(a1.x, aj.x, gp1[t]);
            gp1[t] = fma2(a1.y, aj.y, gp1[t]);
        }
    }
    float g0[4], g1[4];
#pragma unroll
    for (int t = 0; t < 4; t++) {
        float lo, hi;
        upk2(gp0[t], lo, hi); g0[t] = lo + hi;
        upk2(gp1[t], lo, hi); g1[t] = lo + hi;
    }

    float rs0 = fabsf(g0[0]) + fabsf(g0[1]) + fabsf(g0[2]) + fabsf(g0[3]);
    float rs1 = fabsf(g1[0]) + fabsf(g1[1]) + fabsf(g1[2]) + fabsf(g1[3]);
    rs0 += __shfl_xor_sync(0xffffffffu, rs0, 1);
    rs0 += __shfl_xor_sync(0xffffffffu, rs0, 2);
    rs1 += __shfl_xor_sync(0xffffffffu, rs1, 1);
    rs1 += __shfl_xor_sync(0xffffffffu, rs1, 2);
    float rs = fmaxf(rs0, rs1);
    rs = fmaxf(rs, __shfl_xor_sync(0xffffffffu, rs, 4));
    rs = fmaxf(rs, __shfl_xor_sync(0xffffffffu, rs, 8));
    rs = fmaxf(rs, __shfl_xor_sync(0xffffffffu, rs, 16));
    float invs = 1.0f / rs;

#pragma unroll
    for (int t = 0; t < 4; t++) { g0[t] *= invs; g1[t] *= invs; }
    *(float4*)&Ym[i0][j0]     = make_float4(g0[0], g0[1], g0[2], g0[3]);
    *(float4*)&Ym[i0 + 1][j0] = make_float4(g1[0], g1[1], g1[2], g1[3]);
    __syncwarp();

    int ntot = nspecial + nclassic;

    {
        float ca = (0 < nspecial) ? ca_s : 1.5f;
        float cb = (0 < nspecial) ? cb_s : -0.5f;
        u64p cap = pk2(ca, ca), cbp = pk2(cb, cb);
        float yr0[16], yr1[16];
#pragma unroll
        for (int qq = 0; qq < 4; qq++) {
            float4 a = *(const float4*)&Ym[i0][qq * 4];
            float4 bqq = *(const float4*)&Ym[i0 + 1][qq * 4];
            yr0[qq * 4 + 0] = a.x; yr0[qq * 4 + 1] = a.y;
            yr0[qq * 4 + 2] = a.z; yr0[qq * 4 + 3] = a.w;
            yr1[qq * 4 + 0] = bqq.x; yr1[qq * 4 + 1] = bqq.y;
            yr1[qq * 4 + 2] = bqq.z; yr1[qq * 4 + 3] = bqq.w;
        }
        u64p s0p[2] = {0ull, 0ull}, s1p[2] = {0ull, 0ull};
#pragma unroll
        for (int k = 0; k < 16; k++) {
            u64p yap = pk2(yr0[k], yr0[k]), ybp = pk2(yr1[k], yr1[k]);
            ulonglong2 y2 = *(const ulonglong2*)&Ym[k][j0];
            s0p[0] = fma2(yap, y2.x, s0p[0]); s0p[1] = fma2(yap, y2.y, s0p[1]);
            s1p[0] = fma2(ybp, y2.x, s1p[0]); s1p[1] = fma2(ybp, y2.y, s1p[1]);
        }
        __syncwarp();
        u64p yo0x = pk2(g0[0], g0[1]), yo0y = pk2(g0[2], g0[3]);
        u64p yo1x = pk2(g1[0], g1[1]), yo1y = pk2(g1[2], g1[3]);
        ulonglong2 ny;
        ny.x = fma2(cbp, s0p[0], mul2(cap, yo0x));
        ny.y = fma2(cbp, s0p[1], mul2(cap, yo0y));
        *(ulonglong2*)&Ym[i0][j0] = ny;
        ny.x = fma2(cbp, s1p[0], mul2(cap, yo1x));
        ny.y = fma2(cbp, s1p[1], mul2(cap, yo1y));
        *(ulonglong2*)&Ym[i0 + 1][j0] = ny;
        *(float4*)&Zm[i0][j0] = make_float4(
            (i0 == j0 ? ca : 0.f) + cb * g0[0], (i0 == j0 + 1 ? ca : 0.f) + cb * g0[1],
            (i0 == j0 + 2 ? ca : 0.f) + cb * g0[2], (i0 == j0 + 3 ? ca : 0.f) + cb * g0[3]);
        *(float4*)&Zm[i0 + 1][j0] = make_float4(
            (i0 + 1 == j0 ? ca : 0.f) + cb * g1[0], (i0 + 1 == j0 + 1 ? ca : 0.f) + cb * g1[1],
            (i0 + 1 == j0 + 2 ? ca : 0.f) + cb * g1[2], (i0 + 1 == j0 + 3 ? ca : 0.f) + cb * g1[3]);
        __syncwarp();
    }

    for (int it = 1; it < ntot; it++) {
        float ca = (it < nspecial) ? ca_s : 1.5f;
        float cb = (it < nspecial) ? cb_s : -0.5f;
        bool lastit = (it == ntot - 1);
        u64p cap = pk2(ca, ca), cbp = pk2(cb, cb);

        float zr0[16], zr1[16];
#pragma unroll
        for (int qq = 0; qq < 4; qq++) {
            float4 a = *(const float4*)&Zm[i0][qq * 4];
            float4 bqq = *(const float4*)&Zm[i0 + 1][qq * 4];
            zr0[qq * 4 + 0] = a.x; zr0[qq * 4 + 1] = a.y;
            zr0[qq * 4 + 2] = a.z; zr0[qq * 4 + 3] = a.w;
            zr1[qq * 4 + 0] = bqq.x; zr1[qq * 4 + 1] = bqq.y;
            zr1[qq * 4 + 2] = bqq.z; zr1[qq * 4 + 3] = bqq.w;
        }

        {
            u64p t0p[2] = {0ull, 0ull}, t1p[2] = {0ull, 0ull};
#pragma unroll
            for (int k = 0; k < 16; k++) {
                u64p z0p = pk2(zr0[k], zr0[k]), z1p = pk2(zr1[k], zr1[k]);
                ulonglong2 y2 = *(const ulonglong2*)&Ym[k][j0];
                t0p[0] = fma2(z0p, y2.x, t0p[0]); t0p[1] = fma2(z0p, y2.y, t0p[1]);
                t1p[0] = fma2(z1p, y2.x, t1p[0]); t1p[1] = fma2(z1p, y2.y, t1p[1]);
            }
            ulonglong2 tw;
            tw.x = t0p[0]; tw.y = t0p[1];
            *(ulonglong2*)&Tm[i0][j0] = tw;
            tw.x = t1p[0]; tw.y = t1p[1];
            *(ulonglong2*)&Tm[i0 + 1][j0] = tw;
        }
        __syncwarp();

        float yr0[16], yr1[16];
        if (!lastit) {
#pragma unroll
            for (int qq = 0; qq < 4; qq++) {
                float4 a = *(const float4*)&Ym[i0][qq * 4];
                float4 bqq = *(const float4*)&Ym[i0 + 1][qq * 4];
                yr0[qq * 4 + 0] = a.x; yr0[qq * 4 + 1] = a.y;
                yr0[qq * 4 + 2] = a.z; yr0[qq * 4 + 3] = a.w;
                yr1[qq * 4 + 0] = bqq.x; yr1[qq * 4 + 1] = bqq.y;
                yr1[qq * 4 + 2] = bqq.z; yr1[qq * 4 + 3] = bqq.w;
            }
        }

        u64p zn0p[2] = {0ull, 0ull}, zn1p[2] = {0ull, 0ull};
        u64p yn0p[2] = {0ull, 0ull}, yn1p[2] = {0ull, 0ull};
#pragma unroll
        for (int k = 0; k < 16; k++) {
            ulonglong2 m2 = *(const ulonglong2*)&Tm[k][j0];
            u64p zap = pk2(zr0[k], zr0[k]), zbp = pk2(zr1[k], zr1[k]);
            zn0p[0] = fma2(zap, m2.x, zn0p[0]); zn0p[1] = fma2(zap, m2.y, zn0p[1]);
            zn1p[0] = fma2(zbp, m2.x, zn1p[0]); zn1p[1] = fma2(zbp, m2.y, zn1p[1]);
            if (!lastit) {
                u64p yap = pk2(yr0[k], yr0[k]), ybp = pk2(yr1[k], yr1[k]);
                yn0p[0] = fma2(yap, m2.x, yn0p[0]); yn0p[1] = fma2(yap, m2.y, yn0p[1]);
                yn1p[0] = fma2(ybp, m2.x, yn1p[0]); yn1p[1] = fma2(ybp, m2.y, yn1p[1]);
            }
        }
        ulonglong2 zc0 = *(const ulonglong2*)&Zm[i0][j0];
        ulonglong2 zc1 = *(const ulonglong2*)&Zm[i0 + 1][j0];
        ulonglong2 yc0, yc1;
        if (!lastit) {
            yc0 = *(const ulonglong2*)&Ym[i0][j0];
            yc1 = *(const ulonglong2*)&Ym[i0 + 1][j0];
        }
        __syncwarp();
        ulonglong2 o;
        o.x = fma2(cbp, zn0p[0], mul2(cap, zc0.x));
        o.y = fma2(cbp, zn0p[1], mul2(cap, zc0.y));
        *(ulonglong2*)&Zm[i0][j0] = o;
        o.x = fma2(cbp, zn1p[0], mul2(cap, zc1.x));
        o.y = fma2(cbp, zn1p[1], mul2(cap, zc1.y));
        *(ulonglong2*)&Zm[i0 + 1][j0] = o;
        if (!lastit) {
            o.x = fma2(cbp, yn0p[0], mul2(cap, yc0.x));
            o.y = fma2(cbp, yn0p[1], mul2(cap, yc0.y));
            *(ulonglong2*)&Ym[i0][j0] = o;
            o.x = fma2(cbp, yn1p[0], mul2(cap, yc1.x));
            o.y = fma2(cbp, yn1p[1], mul2(cap, yc1.y));
            *(ulonglong2*)&Ym[i0 + 1][j0] = o;
        }
        __syncwarp();
    }

    float isq = rsqrtf(rs);
    u64p isqp = pk2(isq, isq);
    u64p u0p[8], u1p[8];
#pragma unroll
    for (int j = 0; j < 8; j++) { u0p[j] = 0ull; u1p[j] = 0ull; }
#pragma unroll
    for (int k = 0; k < 16; k++) {
        float2 a2 = *(const float2*)&A[k][r0];
        u64p a0p = pk2(a2.x, a2.x);
        u64p a1p = pk2(a2.y, a2.y);
#pragma unroll
        for (int cq = 0; cq < 4; cq++) {
            ulonglong2 z2 = *(const ulonglong2*)&Zm[k][cq * 4];
            u0p[cq * 2]     = fma2(a0p, z2.x, u0p[cq * 2]);
            u0p[cq * 2 + 1] = fma2(a0p, z2.y, u0p[cq * 2 + 1]);
            u1p[cq * 2]     = fma2(a1p, z2.x, u1p[cq * 2]);
            u1p[cq * 2 + 1] = fma2(a1p, z2.y, u1p[cq * 2 + 1]);
        }
    }
#pragma unroll
    for (int j = 0; j < 8; j++) {
        u0p[j] = mul2(u0p[j], isqp);
        u1p[j] = mul2(u1p[j], isqp);
    }

#pragma unroll
    for (int cq = 0; cq < 4; cq++) {
        ulonglong2 s0, s1;
        s0.x = u0p[cq * 2]; s0.y = u0p[cq * 2 + 1];
        s1.x = u1p[cq * 2]; s1.y = u1p[cq * 2 + 1];
        *(ulonglong2*)(dst + r0 * 16 + cq * 4)       = s0;
        *(ulonglong2*)(dst + (r0 + 1) * 16 + cq * 4) = s1;
    }

    {
        __half* gh = g_hX[opar] + doff;
        uint32_t p[8];
#pragma unroll
        for (int j = 0; j < 8; j++) {
            float lo, hi;
            upk2(u0p[j], lo, hi);
            __half2 h2;
            h2.x = __float2half_rn(lo);
            h2.y = __float2half_rn(hi);
            p[j] = *(uint32_t*)&h2;
        }
        *(uint4*)(gh + r0 * 16)     = make_uint4(p[0], p[1], p[2], p[3]);
        *(uint4*)(gh + r0 * 16 + 8) = make_uint4(p[4], p[5], p[6], p[7]);
#pragma unroll
        for (int j = 0; j < 8; j++) {
            float lo, hi;
            upk2(u1p[j], lo, hi);
            __half2 h2;
            h2.x = __float2half_rn(lo);
            h2.y = __float2half_rn(hi);
            p[j] = *(uint32_t*)&h2;
        }
        *(uint4*)(gh + (r0 + 1) * 16)     = make_uint4(p[0], p[1], p[2], p[3]);
        *(uint4*)(gh + (r0 + 1) * 16 + 8) = make_uint4(p[4], p[5], p[6], p[7]);
    }
}

// ---------------- X_transformed transpose (float4 stores) --------------------
__global__ void xt_kernel(float* __restrict__ out) {
    __shared__ float tile[256][18];
    int base = blockIdx.x * 256;
    int tid = threadIdx.x;
#pragma unroll
    for (int l = 0; l < 17; l++)
        tile[tid][l] = g_xt[(size_t)l * PLANE + base + tid];
    __syncthreads();
    float4* o4 = (float4*)(out + (size_t)base * 17);
    for (int i = tid; i < 1088; i += 256) {     // 4352 floats = 1088 float4
        int e = i * 4;
        float4 v;
        v.x = tile[e / 17][e % 17];
        v.y = tile[(e + 1) / 17][(e + 1) % 17];
        v.z = tile[(e + 2) / 17][(e + 2) % 17];
        v.w = tile[(e + 3) / 17][(e + 3) % 17];
        o4[i] = v;
    }
}

// ---------------- reconstruct + classify + softmax ----------------------------
__global__ __launch_bounds__(128) void classify_kernel(
    const float* __restrict__ Wc, const float* __restrict__ bc,
    float* __restrict__ out, int off_log)
{
    __shared__ float sU[1024], sS[256], sV[1024], sT[1024];
    __shared__ float sZ[4096];
    __shared__ float red[10 * 136];
    __shared__ float slog[10];

    int b = blockIdx.x, tid = threadIdx.x;
    const float* base = g_xt + (size_t)16 * PLANE + (size_t)b * 3 * 1024;

    for (int i = tid; i < 1024; i += 128) { sU[i] = base[i]; sV[i] = base[2048 + i]; }
    for (int i = tid; i < 256; i += 128) sS[i] = base[1024 + i];
    __syncthreads();

    for (int e = tid; e < 1024; e += 128) {
        int r = e >> 4, c = e & 15;
        float sum = 0.f;
#pragma unroll
        for (int k = 0; k < 16; k++) sum += sU[r * 16 + k] * sS[k * 16 + c];
        sT[e] = sum;
    }
    __syncthreads();

    for (int e = tid; e < 4096; e += 128) {
        int r = e >> 6, qn = e & 63;
        float sum = 0.f;
#pragma unroll
        for (int c = 0; c < 16; c++) sum += sT[r * 16 + c] * sV[qn * 16 + c];
        sZ[e] = sum;
    }
    __syncthreads();

    float acc[10];
#pragma unroll
    for (int n = 0; n < 10; n++) acc[n] = 0.f;
    for (int e = tid; e < 4096; e += 128) {
        float z = sZ[e];
#pragma unroll
        for (int n = 0; n < 10; n++) acc[n] += z * Wc[n * 4096 + e];
    }
#pragma unroll
    for (int n = 0; n < 10; n++) red[n * 136 + tid] = acc[n];
    __syncthreads();
    if (tid < 10) {
        float s = bc[tid];
        for (int j = 0; j < 128; j++) s += red[tid * 136 + j];
        slog[tid] = s;
    }
    __syncthreads();
    if (tid == 0) {
        float mx = slog[0];
        for (int n = 1; n < 10; n++) mx = fmaxf(mx, slog[n]);
        float ex[10]; float se = 0.f;
        for (int n = 0; n < 10; n++) { ex[n] = expf(slog[n] - mx); se += ex[n]; }
        float inv = 1.f / se;
        for (int n = 0; n < 10; n++) {
            out[b * 10 + n] = ex[n] * inv;
            if (off_log >= 0) out[off_log + b * 10 + n] = slog[n];
        }
    }
}

// ---------------- launch ------------------------------------------------------
extern "C" void kernel_launch(void* const* d_in, const int* in_sizes, int n_in,
                              void* d_out, int out_size) {
    const float* X  = (const float*)d_in[0];
    const float* h  = (const float*)d_in[1];
    const float* W0 = (const float*)d_in[2];
    const float* Ws = (const float*)d_in[3];
    const float* bs = (const float*)d_in[4];
    const float* Wc = (const float*)d_in[5];
    const float* bc = (const float*)d_in[6];
    float* out = (float*)d_out;

    int off_log = -1, off_xt = -1;
    if (out_size >= 10240 + 10240 + 53477376) { off_log = 10240; off_xt = 20480; }
    else if (out_size == 10240 + 53477376)    { off_xt = 10240; }
    else if (out_size >= 20480)               { off_log = 10240; }

    cudaFuncSetAttribute(tgemm_kernel, cudaFuncAttributeMaxDynamicSharedMemorySize,
                         SMEM_TOTAL_G);

    wconv_kernel<<<WELEMS / 256, 256>>>(W0, Ws);
    prep_kernel<<<PLANE / 256, 256>>>(X);

    tgemm_kernel<<<256, 256, SMEM_TOTAL_G>>>(nullptr, h, 0);
    polar_kernel<<<512, 128>>>(0, 4, 5, 2.4f, -1.4f, 1);   // layer 0: 4 agg + 5 classic
    for (int l = 1; l <= 16; l++) {
        tgemm_kernel<<<256, 256, SMEM_TOTAL_G>>>(bs + (size_t)(l - 1) * 1024, h, l);
        polar_kernel<<<512, 128>>>(l, 1, 2, 1.9f, -0.9f, (l + 1) & 1);
    }

    if (off_xt >= 0)
        xt_kernel<<<PLANE / 256, 256>>>(out + off_xt);
    classify_kernel<<<1024, 128>>>(Wc, bc, out, off_log);
}

// round 17
// speedup vs baseline: 1.0058x; 1.0058x over previous
#include <cuda_runtime.h>
#include <cuda_fp16.h>
#include <math.h>
#include <stdint.h>

#define PLANE 3145728            // 3072 * 1024
#define WELEMS 17825792          // 17 * 1024 * 1024

// ---------------- device scratch --------------------------------------------
__device__ float g_Y[PLANE];                 // pre-projection Y of current layer
__device__ float g_xt[17 * PLANE];           // xs[l] planes (fp32)
__device__ __half g_hX[2][PLANE];            // ping-pong fp16 X
__device__ __half g_hW[WELEMS];              // fp16 weights (W0 at 0, Ws at 1..16)

// ---------------- helpers -----------------------------------------------------
typedef unsigned long long u64p;

static __device__ __forceinline__ uint32_t smem_u32(const void* p) {
    return (uint32_t)__cvta_generic_to_shared(p);
}
static __device__ __forceinline__ void ldsm4(uint32_t* r, uint32_t addr) {
    asm volatile("ldmatrix.sync.aligned.m8n8.x4.shared.b16 {%0,%1,%2,%3}, [%4];"
        : "=r"(r[0]), "=r"(r[1]), "=r"(r[2]), "=r"(r[3]) : "r"(addr));
}
static __device__ __forceinline__ void mma16816(float* c, const uint32_t* a,
                                                uint32_t b0, uint32_t b1) {
    asm volatile("mma.sync.aligned.m16n8k16.row.col.f32.f16.f16.f32 "
        "{%0,%1,%2,%3}, {%4,%5,%6,%7}, {%8,%9}, {%0,%1,%2,%3};"
        : "+f"(c[0]), "+f"(c[1]), "+f"(c[2]), "+f"(c[3])
        : "r"(a[0]), "r"(a[1]), "r"(a[2]), "r"(a[3]), "r"(b0), "r"(b1));
}
static __device__ __forceinline__ u64p pk2(float x, float y) {
    u64p r; asm("mov.b64 %0, {%1,%2};" : "=l"(r) : "f"(x), "f"(y)); return r;
}
static __device__ __forceinline__ void upk2(u64p v, float& x, float& y) {
    asm("mov.b64 {%0,%1}, %2;" : "=f"(x), "=f"(y) : "l"(v));
}
static __device__ __forceinline__ u64p fma2(u64p a, u64p b, u64p c) {
    u64p d; asm("fma.rn.f32x2 %0, %1, %2, %3;" : "=l"(d) : "l"(a), "l"(b), "l"(c));
    return d;
}
static __device__ __forceinline__ u64p mul2(u64p a, u64p b) {
    u64p d; asm("mul.rn.f32x2 %0, %1, %2;" : "=l"(d) : "l"(a), "l"(b));
    return d;
}

// ---------------- weight conversion + input prep (merged) --------------------
__global__ void wp_kernel(const float* __restrict__ W0, const float* __restrict__ Ws,
                          const float* __restrict__ Xin) {
    size_t i = (size_t)blockIdx.x * 256 + threadIdx.x;
    if (i < (size_t)WELEMS) {
        float v = (i < 1048576) ? W0[i] : Ws[i - 1048576];
        g_hW[i] = __float2half_rn(v);
    } else {
        int idx = (int)(i - WELEMS);
        if (idx >= PLANE) return;
        int d  = idx & 1023;
        int bc = idx >> 10;
        int c  = bc % 3;
        float v;
        if (c == 2) {
            int b = bc / 3;
            int dim = d >> 4, k = d & 15;
            v = Xin[((size_t)(b * 3 + 2)) * 1024 + k * 64 + dim];
        } else {
            v = Xin[idx];
        }
        g_hX[0][idx] = __float2half_rn(v);
    }
}

// ---------------- fp16 mma.sync GEMM + fused epilogue ------------------------
// Tile 96x128 (256 CTAs), K-chunk 64, 3-stage cp.async, 8 warps (2M x 4N).
#define MAT_STRIDE_B 144                 // bytes per smem row (128B data + pad)
#define A_BYTES (96 * MAT_STRIDE_B)      // 13824
#define B_BYTES (128 * MAT_STRIDE_B)     // 18432
#define STAGE_BYTES (A_BYTES + B_BYTES)  // 32256
#define SMEM_TOTAL_G (3 * STAGE_BYTES)   // 96768

__global__ __launch_bounds__(256, 2) void tgemm_kernel(
    const float* __restrict__ bias, const float* __restrict__ hp, int layer)
{
    extern __shared__ __align__(16) char smem[];
    uint32_t sb = smem_u32(smem);

    int tid = threadIdx.x;
    int wid = tid >> 5, lane = tid & 31;
    int bx = blockIdx.x;
    int m0 = (bx >> 3) * 96;
    int n0 = (bx & 7) * 128;

    int par = layer & 1;
    const __half* srcA = g_hX[par] + (size_t)m0 * 1024;
    const __half* srcB = g_hW + (size_t)layer * 1048576 + (size_t)n0 * 1024;

    float acc[3][4][4];
#pragma unroll
    for (int i = 0; i < 3; i++)
#pragma unroll
        for (int j = 0; j < 4; j++)
#pragma unroll
            for (int k = 0; k < 4; k++) acc[i][j][k] = 0.f;

    auto issue = [&](int c, int st) {
#pragma unroll
        for (int u = 0; u < 7; u++) {
            int unit = tid + u * 256;        // 0..1791
            uint32_t dst;
            const __half* gp;
            if (unit < 768) {                // A: 96 rows x 8 segs
                int row = unit >> 3, seg = unit & 7;
                dst = sb + st * STAGE_BYTES + row * MAT_STRIDE_B + seg * 16;
                gp = srcA + (size_t)row * 1024 + c * 64 + seg * 8;
            } else {                         // B: 128 rows x 8 segs
                int t = unit - 768;
                int row = t >> 3, seg = t & 7;
                dst = sb + st * STAGE_BYTES + A_BYTES + row * MAT_STRIDE_B + seg * 16;
                gp = srcB + (size_t)row * 1024 + c * 64 + seg * 8;
            }
            asm volatile("cp.async.cg.shared.global [%0], [%1], 16;"
                :: "r"(dst), "l"(gp));
        }
        asm volatile("cp.async.commit_group;" ::: "memory");
    };

    issue(0, 0);
    issue(1, 1);

    int mw = (wid >> 2) * 48, nw = (wid & 3) * 32;
    int lrow = (lane & 7) + ((lane >> 3) & 1) * 8;
    int lcolB = ((lane >> 4) * 8) * 2;

    for (int c = 0; c < 16; c++) {
        int st = c % 3;
        if (c < 15) {
            asm volatile("cp.async.wait_group 1;" ::: "memory");
        } else {
            asm volatile("cp.async.wait_group 0;" ::: "memory");
        }
        __syncthreads();
        if (c + 2 < 16) issue(c + 2, (c + 2) % 3);

        uint32_t base = sb + st * STAGE_BYTES;
#pragma unroll
        for (int ks = 0; ks < 4; ks++) {
            int colb = ks * 32 + lcolB;
            uint32_t bh[2][4];
#pragma unroll
            for (int nb = 0; nb < 2; nb++)
                ldsm4(bh[nb], base + A_BYTES +
                              (nw + nb * 16 + lrow) * MAT_STRIDE_B + colb);
#pragma unroll
            for (int ma = 0; ma < 3; ma++) {
                uint32_t ah[4];
                ldsm4(ah, base + (mw + ma * 16 + lrow) * MAT_STRIDE_B + colb);
#pragma unroll
                for (int na = 0; na < 4; na++) {
                    int nb = na >> 1, hi = na & 1;
                    mma16816(acc[ma][na], ah, bh[nb][hi], bh[nb][2 + hi]);
                }
            }
        }
    }

    // ---- fused epilogue (bias hoisted: depends only on na)
    float hv = 0.f;
    const float* Xprev = nullptr;
    if (layer > 0) { hv = *hp; Xprev = g_xt + (size_t)(layer - 1) * PLANE; }
    float* PL = g_xt + (size_t)layer * PLANE;
    int opar = (layer + 1) & 1;
    int g = lane >> 2, t2 = (lane & 3) * 2;

    float2 bb[4];
#pragma unroll
    for (int na = 0; na < 4; na++) {
        bb[na] = make_float2(0.f, 0.f);
        if (layer > 0) bb[na] = *(const float2*)(bias + n0 + nw + na * 8 + t2);
    }

#pragma unroll
    for (int ma = 0; ma < 3; ma++) {
#pragma unroll
        for (int na = 0; na < 4; na++) {
            int n = n0 + nw + na * 8 + t2;
            float2 b2 = bb[na];
#pragma unroll
            for (int hh = 0; hh < 2; hh++) {
                int m = m0 + mw + ma * 16 + g + hh * 8;
                float cx = acc[ma][na][hh * 2], cy = acc[ma][na][hh * 2 + 1];
                float2 y;
                if (layer > 0) {
                    float2 xo = *(const float2*)(Xprev + (size_t)m * 1024 + n);
                    y.x = xo.x + hv * fmaxf(cx + b2.x, 0.f);
                    y.y = xo.y + hv * fmaxf(cy + b2.y, 0.f);
                } else {
                    y.x = cx; y.y = cy;
                }
                if (m % 3 == 1) {          // S channel: no projection
                    *(float2*)(PL + (size_t)m * 1024 + n) = y;
                    __half2 h2;
                    h2.x = __float2half_rn(y.x);
                    h2.y = __float2half_rn(y.y);
                    *(__half2*)(&g_hX[opar][(size_t)m * 1024 + n]) = h2;
                } else {                   // U/V channels: polar input only
                    *(float2*)(g_Y + (size_t)m * 1024 + n) = y;
                }
            }
        }
    }
}

// ---------------- polar projection (NS, smem-op minimized) -------------------
#define PNW 4
__global__ __launch_bounds__(128) void polar_kernel(int plane, int nspecial,
                                                    int nclassic, float ca_s,
                                                    float cb_s, int opar) {
    __shared__ float AsP[PNW][16][68];
    __shared__ float MsP[PNW][3][16][20];

    int w = threadIdx.x >> 5, lane = threadIdx.x & 31;
    int idx = blockIdx.x * PNW + w;
    int b = idx >> 1, ch = (idx & 1) * 2;

    const float* src = g_Y + (size_t)(b * 3 + ch) * 1024;
    size_t doff = (size_t)(b * 3 + ch) * 1024;
    float* dst = g_xt + (size_t)plane * PLANE + doff;

    float (*A)[68]  = AsP[w];
    float (*Ym)[20] = MsP[w][0];
    float (*Zm)[20] = MsP[w][1];
    float (*Tm)[20] = MsP[w][2];

    int r0 = lane * 2;
#pragma unroll
    for (int qq = 0; qq < 4; qq++) {
        float4 v0 = *(const float4*)(src + r0 * 16 + qq * 4);
        float4 v1 = *(const float4*)(src + (r0 + 1) * 16 + qq * 4);
        *(float2*)&A[qq * 4 + 0][r0] = make_float2(v0.x, v1.x);
        *(float2*)&A[qq * 4 + 1][r0] = make_float2(v0.y, v1.y);
        *(float2*)&A[qq * 4 + 2][r0] = make_float2(v0.z, v1.z);
        *(float2*)&A[qq * 4 + 3][r0] = make_float2(v0.w, v1.w);
    }
    __syncwarp();

    int i0 = (lane >> 2) * 2, j0 = (lane & 3) * 4;

    u64p gp0[4], gp1[4];
#pragma unroll
    for (int t = 0; t < 4; t++) { gp0[t] = 0ull; gp1[t] = 0ull; }
#pragma unroll
    for (int r = 0; r < 64; r += 4) {
        ulonglong2 a0 = *(const ulonglong2*)&A[i0][r];
        ulonglong2 a1 = *(const ulonglong2*)&A[i0 + 1][r];
#pragma unroll
        for (int t = 0; t < 4; t++) {
            ulonglong2 aj = *(const ulonglong2*)&A[j0 + t][r];
            gp0[t] = fma2(a0.x, aj.x, gp0[t]);
            gp0[t] = fma2(a0.y, aj.y, gp0[t]);
            gp1[t] = fma2(a1.x, aj.x, gp1[t]);
            gp1[t] = fma2(a1.y, aj.y, gp1[t]);
        }
    }
    float g0[4], g1[4];
#pragma unroll
    for (int t = 0; t < 4; t++) {
        float lo, hi;
        upk2(gp0[t], lo, hi); g0[t] = lo + hi;
        upk2(gp1[t], lo, hi); g1[t] = lo + hi;
    }

    float rs0 = fabsf(g0[0]) + fabsf(g0[1]) + fabsf(g0[2]) + fabsf(g0[3]);
    float rs1 = fabsf(g1[0]) + fabsf(g1[1]) + fabsf(g1[2]) + fabsf(g1[3]);
    rs0 += __shfl_xor_sync(0xffffffffu, rs0, 1);
    rs0 += __shfl_xor_sync(0xffffffffu, rs0, 2);
    rs1 += __shfl_xor_sync(0xffffffffu, rs1, 1);
    rs1 += __shfl_xor_sync(0xffffffffu, rs1, 2);
    float rs = fmaxf(rs0, rs1);
    rs = fmaxf(rs, __shfl_xor_sync(0xffffffffu, rs, 4));
    rs = fmaxf(rs, __shfl_xor_sync(0xffffffffu, rs, 8));
    rs = fmaxf(rs, __shfl_xor_sync(0xffffffffu, rs, 16));
    float invs = 1.0f / rs;

#pragma unroll
    for (int t = 0; t < 4; t++) { g0[t] *= invs; g1[t] *= invs; }
    *(float4*)&Ym[i0][j0]     = make_float4(g0[0], g0[1], g0[2], g0[3]);
    *(float4*)&Ym[i0 + 1][j0] = make_float4(g1[0], g1[1], g1[2], g1[3]);
    __syncwarp();

    int ntot = nspecial + nclassic;

    {
        float ca = (0 < nspecial) ? ca_s : 1.5f;
        float cb = (0 < nspecial) ? cb_s : -0.5f;
        u64p cap = pk2(ca, ca), cbp = pk2(cb, cb);
        float yr0[16], yr1[16];
#pragma unroll
        for (int qq = 0; qq < 4; qq++) {
            float4 a = *(const float4*)&Ym[i0][qq * 4];
            float4 bqq = *(const float4*)&Ym[i0 + 1][qq * 4];
            yr0[qq * 4 + 0] = a.x; yr0[qq * 4 + 1] = a.y;
            yr0[qq * 4 + 2] = a.z; yr0[qq * 4 + 3] = a.w;
            yr1[qq * 4 + 0] = bqq.x; yr1[qq * 4 + 1] = bqq.y;
            yr1[qq * 4 + 2] = bqq.z; yr1[qq * 4 + 3] = bqq.w;
        }
        u64p s0p[2] = {0ull, 0ull}, s1p[2] = {0ull, 0ull};
#pragma unroll
        for (int k = 0; k < 16; k++) {
            u64p yap = pk2(yr0[k], yr0[k]), ybp = pk2(yr1[k], yr1[k]);
            ulonglong2 y2 = *(const ulonglong2*)&Ym[k][j0];
            s0p[0] = fma2(yap, y2.x, s0p[0]); s0p[1] = fma2(yap, y2.y, s0p[1]);
            s1p[0] = fma2(ybp, y2.x, s1p[0]); s1p[1] = fma2(ybp, y2.y, s1p[1]);
        }
        __syncwarp();
        u64p yo0x = pk2(g0[0], g0[1]), yo0y = pk2(g0[2], g0[3]);
        u64p yo1x = pk2(g1[0], g1[1]), yo1y = pk2(g1[2], g1[3]);
        ulonglong2 ny;
        ny.x = fma2(cbp, s0p[0], mul2(cap, yo0x));
        ny.y = fma2(cbp, s0p[1], mul2(cap, yo0y));
        *(ulonglong2*)&Ym[i0][j0] = ny;
        ny.x = fma2(cbp, s1p[0], mul2(cap, yo1x));
        ny.y = fma2(cbp, s1p[1], mul2(cap, yo1y));
        *(ulonglong2*)&Ym[i0 + 1][j0] = ny;
        *(float4*)&Zm[i0][j0] = make_float4(
            (i0 == j0 ? ca : 0.f) + cb * g0[0], (i0 == j0 + 1 ? ca : 0.f) + cb * g0[1],
            (i0 == j0 + 2 ? ca : 0.f) + cb * g0[2], (i0 == j0 + 3 ? ca : 0.f) + cb * g0[3]);
        *(float4*)&Zm[i0 + 1][j0] = make_float4(
            (i0 + 1 == j0 ? ca : 0.f) + cb * g1[0], (i0 + 1 == j0 + 1 ? ca : 0.f) + cb * g1[1],
            (i0 + 1 == j0 + 2 ? ca : 0.f) + cb * g1[2], (i0 + 1 == j0 + 3 ? ca : 0.f) + cb * g1[3]);
        __syncwarp();
    }

    for (int it = 1; it < ntot; it++) {
        float ca = (it < nspecial) ? ca_s : 1.5f;
        float cb = (it < nspecial) ? cb_s : -0.5f;
        bool lastit = (it == ntot - 1);
        u64p cap = pk2(ca, ca), cbp = pk2(cb, cb);

        float zr0[16], zr1[16];
#pragma unroll
        for (int qq = 0; qq < 4; qq++) {
            float4 a = *(const float4*)&Zm[i0][qq * 4];
            float4 bqq = *(const float4*)&Zm[i0 + 1][qq * 4];
            zr0[qq * 4 + 0] = a.x; zr0[qq * 4 + 1] = a.y;
            zr0[qq * 4 + 2] = a.z; zr0[qq * 4 + 3] = a.w;
            zr1[qq * 4 + 0] = bqq.x; zr1[qq * 4 + 1] = bqq.y;
            zr1[qq * 4 + 2] = bqq.z; zr1[qq * 4 + 3] = bqq.w;
        }

        {
            u64p t0p[2] = {0ull, 0ull}, t1p[2] = {0ull, 0ull};
#pragma unroll
            for (int k = 0; k < 16; k++) {
                u64p z0p = pk2(zr0[k], zr0[k]), z1p = pk2(zr1[k], zr1[k]);
                ulonglong2 y2 = *(const ulonglong2*)&Ym[k][j0];
                t0p[0] = fma2(z0p, y2.x, t0p[0]); t0p[1] = fma2(z0p, y2.y, t0p[1]);
                t1p[0] = fma2(z1p, y2.x, t1p[0]); t1p[1] = fma2(z1p, y2.y, t1p[1]);
            }
            ulonglong2 tw;
            tw.x = t0p[0]; tw.y = t0p[1];
            *(ulonglong2*)&Tm[i0][j0] = tw;
            tw.x = t1p[0]; tw.y = t1p[1];
            *(ulonglong2*)&Tm[i0 + 1][j0] = tw;
        }
        __syncwarp();

        float yr0[16], yr1[16];
        if (!lastit) {
#pragma unroll
            for (int qq = 0; qq < 4; qq++) {
                float4 a = *(const float4*)&Ym[i0][qq * 4];
                float4 bqq = *(const float4*)&Ym[i0 + 1][qq * 4];
                yr0[qq * 4 + 0] = a.x; yr0[qq * 4 + 1] = a.y;
                yr0[qq * 4 + 2] = a.z; yr0[qq * 4 + 3] = a.w;
                yr1[qq * 4 + 0] = bqq.x; yr1[qq * 4 + 1] = bqq.y;
                yr1[qq * 4 + 2] = bqq.z; yr1[qq * 4 + 3] = bqq.w;
            }
        }

        u64p zn0p[2] = {0ull, 0ull}, zn1p[2] = {0ull, 0ull};
        u64p yn0p[2] = {0ull, 0ull}, yn1p[2] = {0ull, 0ull};
#pragma unroll
        for (int k = 0; k < 16; k++) {
            ulonglong2 m2 = *(const ulonglong2*)&Tm[k][j0];
            u64p zap = pk2(zr0[k], zr0[k]), zbp = pk2(zr1[k], zr1[k]);
            zn0p[0] = fma2(zap, m2.x, zn0p[0]); zn0p[1] = fma2(zap, m2.y, zn0p[1]);
            zn1p[0] = fma2(zbp, m2.x, zn1p[0]); zn1p[1] = fma2(zbp, m2.y, zn1p[1]);
            if (!lastit) {
                u64p yap = pk2(yr0[k], yr0[k]), ybp = pk2(yr1[k], yr1[k]);
                yn0p[0] = fma2(yap, m2.x, yn0p[0]); yn0p[1] = fma2(yap, m2.y, yn0p[1]);
                yn1p[0] = fma2(ybp, m2.x, yn1p[0]); yn1p[1] = fma2(ybp, m2.y, yn1p[1]);
            }
        }
        ulonglong2 zc0 = *(const ulonglong2*)&Zm[i0][j0];
        ulonglong2 zc1 = *(const ulonglong2*)&Zm[i0 + 1][j0];
        ulonglong2 yc0, yc1;
        if (!lastit) {
            yc0 = *(const ulonglong2*)&Ym[i0][j0];
            yc1 = *(const ulonglong2*)&Ym[i0 + 1][j0];
        }
        __syncwarp();
        ulonglong2 o;
        o.x = fma2(cbp, zn0p[0], mul2(cap, zc0.x));
        o.y = fma2(cbp, zn0p[1], mul2(cap, zc0.y));
        *(ulonglong2*)&Zm[i0][j0] = o;
        o.x = fma2(cbp, zn1p[0], mul2(cap, zc1.x));
        o.y = fma2(cbp, zn1p[1], mul2(cap, zc1.y));
        *(ulonglong2*)&Zm[i0 + 1][j0] = o;
        if (!lastit) {
            o.x = fma2(cbp, yn0p[0], mul2(cap, yc0.x));
            o.y = fma2(cbp, yn0p[1], mul2(cap, yc0.y));
            *(ulonglong2*)&Ym[i0][j0] = o;
            o.x = fma2(cbp, yn1p[0], mul2(cap, yc1.x));
            o.y = fma2(cbp, yn1p[1], mul2(cap, yc1.y));
            *(ulonglong2*)&Ym[i0 + 1][j0] = o;
        }
        __syncwarp();
    }

    float isq = rsqrtf(rs);
    u64p isqp = pk2(isq, isq);
    u64p u0p[8], u1p[8];
#pragma unroll
    for (int j = 0; j < 8; j++) { u0p[j] = 0ull; u1p[j] = 0ull; }
#pragma unroll
    for (int k = 0; k < 16; k++) {
        float2 a2 = *(const float2*)&A[k][r0];
        u64p a0p = pk2(a2.x, a2.x);
        u64p a1p = pk2(a2.y, a2.y);
#pragma unroll
        for (int cq = 0; cq < 4; cq++) {
            ulonglong2 z2 = *(const ulonglong2*)&Zm[k][cq * 4];
            u0p[cq * 2]     = fma2(a0p, z2.x, u0p[cq * 2]);
            u0p[cq * 2 + 1] = fma2(a0p, z2.y, u0p[cq * 2 + 1]);
            u1p[cq * 2]     = fma2(a1p, z2.x, u1p[cq * 2]);
            u1p[cq * 2 + 1] = fma2(a1p, z2.y, u1p[cq * 2 + 1]);
        }
    }
#pragma unroll
    for (int j = 0; j < 8; j++) {
        u0p[j] = mul2(u0p[j], isqp);
        u1p[j] = mul2(u1p[j], isqp);
    }

#pragma unroll
    for (int cq = 0; cq < 4; cq++) {
        ulonglong2 s0, s1;
        s0.x = u0p[cq * 2]; s0.y = u0p[cq * 2 + 1];
        s1.x = u1p[cq * 2]; s1.y = u1p[cq * 2 + 1];
        *(ulonglong2*)(dst + r0 * 16 + cq * 4)       = s0;
        *(ulonglong2*)(dst + (r0 + 1) * 16 + cq * 4) = s1;
    }

    {
        __half* gh = g_hX[opar] + doff;
        uint32_t p[8];
#pragma unroll
        for (int j = 0; j < 8; j++) {
            float lo, hi;
            upk2(u0p[j], lo, hi);
            __half2 h2;
            h2.x = __float2half_rn(lo);
            h2.y = __float2half_rn(hi);
            p[j] = *(uint32_t*)&h2;
        }
        *(uint4*)(gh + r0 * 16)     = make_uint4(p[0], p[1], p[2], p[3]);
        *(uint4*)(gh + r0 * 16 + 8) = make_uint4(p[4], p[5], p[6], p[7]);
#pragma unroll
        for (int j = 0; j < 8; j++) {
            float lo, hi;
            upk2(u1p[j], lo, hi);
            __half2 h2;
            h2.x = __float2half_rn(lo);
            h2.y = __float2half_rn(hi);
            p[j] = *(uint32_t*)&h2;
        }
        *(uint4*)(gh + (r0 + 1) * 16)     = make_uint4(p[0], p[1], p[2], p[3]);
        *(uint4*)(gh + (r0 + 1) * 16 + 8) = make_uint4(p[4], p[5], p[6], p[7]);
    }
}

// ---------------- X_transformed transpose (float4 stores) --------------------
__global__ void xt_kernel(float* __restrict__ out) {
    __shared__ float tile[256][18];
    int base = blockIdx.x * 256;
    int tid = threadIdx.x;
#pragma unroll
    for (int l = 0; l < 17; l++)
        tile[tid][l] = g_xt[(size_t)l * PLANE + base + tid];
    __syncthreads();
    float4* o4 = (float4*)(out + (size_t)base * 17);
    for (int i = tid; i < 1088; i += 256) {     // 4352 floats = 1088 float4
        int e = i * 4;
        float4 v;
        v.x = tile[e / 17][e % 17];
        v.y = tile[(e + 1) / 17][(e + 1) % 17];
        v.z = tile[(e + 2) / 17][(e + 2) % 17];
        v.w = tile[(e + 3) / 17][(e + 3) % 17];
        o4[i] = v;
    }
}

// ---------------- reconstruct + classify + softmax ----------------------------
__global__ __launch_bounds__(128) void classify_kernel(
    const float* __restrict__ Wc, const float* __restrict__ bc,
    float* __restrict__ out, int off_log)
{
    __shared__ float sU[1024], sS[256], sV[1024], sT[1024];
    __shared__ float sZ[4096];
    __shared__ float red[10 * 136];
    __shared__ float slog[10];

    int b = blockIdx.x, tid = threadIdx.x;
    const float* base = g_xt + (size_t)16 * PLANE + (size_t)b * 3 * 1024;

    for (int i = tid; i < 1024; i += 128) { sU[i] = base[i]; sV[i] = base[2048 + i]; }
    for (int i = tid; i < 256; i += 128) sS[i] = base[1024 + i];
    __syncthreads();

    for (int e = tid; e < 1024; e += 128) {
        int r = e >> 4, c = e & 15;
        float sum = 0.f;
#pragma unroll
        for (int k = 0; k < 16; k++) sum += sU[r * 16 + k] * sS[k * 16 + c];
        sT[e] = sum;
    }
    __syncthreads();

    for (int e = tid; e < 4096; e += 128) {
        int r = e >> 6, qn = e & 63;
        float sum = 0.f;
#pragma unroll
        for (int c = 0; c < 16; c++) sum += sT[r * 16 + c] * sV[qn * 16 + c];
        sZ[e] = sum;
    }
    __syncthreads();

    float acc[10];
#pragma unroll
    for (int n = 0; n < 10; n++) acc[n] = 0.f;
    for (int e = tid; e < 4096; e += 128) {
        float z = sZ[e];
#pragma unroll
        for (int n = 0; n < 10; n++) acc[n] += z * Wc[n * 4096 + e];
    }
#pragma unroll
    for (int n = 0; n < 10; n++) red[n * 136 + tid] = acc[n];
    __syncthreads();
    if (tid < 10) {
        float s = bc[tid];
        for (int j = 0; j < 128; j++) s += red[tid * 136 + j];
        slog[tid] = s;
    }
    __syncthreads();
    if (tid == 0) {
        float mx = slog[0];
        for (int n = 1; n < 10; n++) mx = fmaxf(mx, slog[n]);
        float ex[10]; float se = 0.f;
        for (int n = 0; n < 10; n++) { ex[n] = expf(slog[n] - mx); se += ex[n]; }
        float inv = 1.f / se;
        for (int n = 0; n < 10; n++) {
            out[b * 10 + n] = ex[n] * inv;
            if (off_log >= 0) out[off_log + b * 10 + n] = slog[n];
        }
    }
}

// ---------------- launch ------------------------------------------------------
extern "C" void kernel_launch(void* const* d_in, const int* in_sizes, int n_in,
                              void* d_out, int out_size) {
    const float* X  = (const float*)d_in[0];
    const float* h  = (const float*)d_in[1];
    const float* W0 = (const float*)d_in[2];
    const float* Ws = (const float*)d_in[3];
    const float* bs = (const float*)d_in[4];
    const float* Wc = (const float*)d_in[5];
    const float* bc = (const float*)d_in[6];
    float* out = (float*)d_out;

    int off_log = -1, off_xt = -1;
    if (out_size >= 10240 + 10240 + 53477376) { off_log = 10240; off_xt = 20480; }
    else if (out_size == 10240 + 53477376)    { off_xt = 10240; }
    else if (out_size >= 20480)               { off_log = 10240; }

    cudaFuncSetAttribute(tgemm_kernel, cudaFuncAttributeMaxDynamicSharedMemorySize,
                         SMEM_TOTAL_G);

    wp_kernel<<<(WELEMS + PLANE) / 256, 256>>>(W0, Ws, X);

    tgemm_kernel<<<256, 256, SMEM_TOTAL_G>>>(nullptr, h, 0);
    polar_kernel<<<512, 128>>>(0, 4, 5, 2.4f, -1.4f, 1);   // layer 0: 4 agg + 5 classic
    for (int l = 1; l <= 16; l++) {
        tgemm_kernel<<<256, 256, SMEM_TOTAL_G>>>(bs + (size_t)(l - 1) * 1024, h, l);
        polar_kernel<<<512, 128>>>(l, 1, 2, 1.9f, -0.9f, (l + 1) & 1);
    }

    if (off_xt >= 0)
        xt_kernel<<<PLANE / 256, 256>>>(out + off_xt);
    classify_kernel<<<1024, 128>>>(Wc, bc, out, off_log);
}